// round 16
// baseline (speedup 1.0000x reference)
#include <cuda_runtime.h>
#include <math.h>

#define NTOT 2048          // B*N
#define KSEL 20

__device__ float  g_xlxr[NTOT * 512];     // [g][0:256)=xl (xr half unused)
__device__ float  g_xrT[4 * 256 * 512];   // [b][d][j] transposed xr

// ---------------- packed f32x2 helpers ----------------
__device__ __forceinline__ double fma2(double a, double b, double c) {
    double d;
    asm("fma.rn.f32x2 %0, %1, %2, %3;" : "=d"(d) : "d"(a), "d"(b), "d"(c));
    return d;
}
__device__ __forceinline__ double add2(double a, double b) {
    double d;
    asm("add.rn.f32x2 %0, %1, %2;" : "=d"(d) : "d"(a), "d"(b));
    return d;
}
__device__ __forceinline__ double abs2(double a) {
    return __longlong_as_double(__double_as_longlong(a) & 0x7fffffff7fffffffULL);
}
__device__ __forceinline__ double dup2(float v) {
    double d;
    asm("mov.b64 %0, {%1, %1};" : "=d"(d) : "f"(v));
    return d;
}
__device__ __forceinline__ float2 unpack2(double a) {
    float2 f;
    asm("mov.b64 {%0, %1}, %2;" : "=f"(f.x), "=f"(f.y) : "d"(a));
    return f;
}

// ---------------------------------------------------------------------------
// Kernel 1: FULL-K projection GEMM + fused output routing (R15, unchanged).
// ---------------------------------------------------------------------------
#define AS_OFF(s) ((s) * 2112)            // 16*132
#define BS_OFF(s) (4224 + (s) * 1088)     // 16*68

__global__ __launch_bounds__(256, 3) void proj_kernel(
    const float* __restrict__ x,
    const float* __restrict__ Wl, const float* __restrict__ bl,
    const float* __restrict__ Wr, const float* __restrict__ br)
{
    __shared__ __align__(16) float pool[8448];   // max(6400 gemm, 8448 T)
    const int tid = threadIdx.x;
    const int tx = tid & 15;
    const int ty = tid >> 4;
    const int g0 = blockIdx.x * 128;
    const int n0 = blockIdx.y * 64;
    const float* W    = (n0 < 256) ? Wl : Wr;
    const float* bias = (n0 < 256) ? bl : br;
    const int nw0 = (n0 < 256) ? n0 : n0 - 256;

    const int lmA = tid >> 1;
    const int lkA = (tid & 1) * 8;
    const int lmB = tid >> 2;
    const int lkB = (tid & 3) * 4;

    const float* xp = &x[(g0 + lmA) * 256 + lkA];
    const float* wp = &W[(nw0 + lmB) * 256 + lkB];

    double acc[8][2];
#pragma unroll
    for (int i = 0; i < 8; ++i) { acc[i][0] = 0.0; acc[i][1] = 0.0; }

    float4 a0 = *(const float4*)xp;
    float4 a1 = *(const float4*)(xp + 4);
    float4 bv = *(const float4*)wp;
    {
        float* A = pool + AS_OFF(0); float* B = pool + BS_OFF(0);
        A[(lkA + 0) * 132 + lmA] = a0.x; A[(lkA + 1) * 132 + lmA] = a0.y;
        A[(lkA + 2) * 132 + lmA] = a0.z; A[(lkA + 3) * 132 + lmA] = a0.w;
        A[(lkA + 4) * 132 + lmA] = a1.x; A[(lkA + 5) * 132 + lmA] = a1.y;
        A[(lkA + 6) * 132 + lmA] = a1.z; A[(lkA + 7) * 132 + lmA] = a1.w;
        B[(lkB + 0) * 68 + lmB] = bv.x;  B[(lkB + 1) * 68 + lmB] = bv.y;
        B[(lkB + 2) * 68 + lmB] = bv.z;  B[(lkB + 3) * 68 + lmB] = bv.w;
    }
    a0 = *(const float4*)(xp + 16);
    a1 = *(const float4*)(xp + 20);
    bv = *(const float4*)(wp + 16);

#pragma unroll 1
    for (int t = 0; t < 16; ++t) {
        __syncthreads();
        if (t < 15) {
            float* A = pool + AS_OFF((t + 1) & 1); float* B = pool + BS_OFF((t + 1) & 1);
            A[(lkA + 0) * 132 + lmA] = a0.x; A[(lkA + 1) * 132 + lmA] = a0.y;
            A[(lkA + 2) * 132 + lmA] = a0.z; A[(lkA + 3) * 132 + lmA] = a0.w;
            A[(lkA + 4) * 132 + lmA] = a1.x; A[(lkA + 5) * 132 + lmA] = a1.y;
            A[(lkA + 6) * 132 + lmA] = a1.z; A[(lkA + 7) * 132 + lmA] = a1.w;
            B[(lkB + 0) * 68 + lmB] = bv.x;  B[(lkB + 1) * 68 + lmB] = bv.y;
            B[(lkB + 2) * 68 + lmB] = bv.z;  B[(lkB + 3) * 68 + lmB] = bv.w;
        }
        if (t < 14) {
            a0 = *(const float4*)(xp + (t + 2) * 16);
            a1 = *(const float4*)(xp + (t + 2) * 16 + 4);
            bv = *(const float4*)(wp + (t + 2) * 16);
        }
        const float* A = pool + AS_OFF(t & 1); const float* B = pool + BS_OFF(t & 1);
#pragma unroll
        for (int k = 0; k < 16; ++k) {
            const float4 r0 = *(const float4*)&A[k * 132 + ty * 8];
            const float4 r1 = *(const float4*)&A[k * 132 + ty * 8 + 4];
            const double2 b2 = *(const double2*)&B[k * 68 + tx * 4];
            double d;
            d = dup2(r0.x); acc[0][0] = fma2(d, b2.x, acc[0][0]);
                            acc[0][1] = fma2(d, b2.y, acc[0][1]);
            d = dup2(r0.y); acc[1][0] = fma2(d, b2.x, acc[1][0]);
                            acc[1][1] = fma2(d, b2.y, acc[1][1]);
            d = dup2(r0.z); acc[2][0] = fma2(d, b2.x, acc[2][0]);
                            acc[2][1] = fma2(d, b2.y, acc[2][1]);
            d = dup2(r0.w); acc[3][0] = fma2(d, b2.x, acc[3][0]);
                            acc[3][1] = fma2(d, b2.y, acc[3][1]);
            d = dup2(r1.x); acc[4][0] = fma2(d, b2.x, acc[4][0]);
                            acc[4][1] = fma2(d, b2.y, acc[4][1]);
            d = dup2(r1.y); acc[5][0] = fma2(d, b2.x, acc[5][0]);
                            acc[5][1] = fma2(d, b2.y, acc[5][1]);
            d = dup2(r1.z); acc[6][0] = fma2(d, b2.x, acc[6][0]);
                            acc[6][1] = fma2(d, b2.y, acc[6][1]);
            d = dup2(r1.w); acc[7][0] = fma2(d, b2.x, acc[7][0]);
                            acc[7][1] = fma2(d, b2.y, acc[7][1]);
        }
    }

    const float b0 = bias[nw0 + tx * 4 + 0];
    const float b1 = bias[nw0 + tx * 4 + 1];
    const float b2f = bias[nw0 + tx * 4 + 2];
    const float b3 = bias[nw0 + tx * 4 + 3];

    if (n0 < 256) {
#pragma unroll
        for (int i = 0; i < 8; ++i) {
            const int row = g0 + ty * 8 + i;
            const float2 p0 = unpack2(acc[i][0]);
            const float2 p1 = unpack2(acc[i][1]);
            *(float4*)&g_xlxr[(size_t)row * 512 + n0 + tx * 4] =
                make_float4(p0.x + b0, p0.y + b1, p1.x + b2f, p1.y + b3);
        }
    } else {
        const int d0 = n0 - 256;
        const int b = g0 >> 9;
        const int j0 = g0 & 511;
        __syncthreads();
        float* T = pool;                  // [64 d][132 j-stride]
#pragma unroll
        for (int c = 0; c < 4; ++c) {
            float r[8];
#pragma unroll
            for (int i = 0; i < 8; ++i) {
                const float2 p = unpack2(acc[i][c >> 1]);
                r[i] = ((c & 1) ? p.y : p.x) + ((c == 0) ? b0 : (c == 1) ? b1
                                              : (c == 2) ? b2f : b3);
            }
            float* dst = &T[(tx * 4 + c) * 132 + ty * 8];
            *(float4*)dst       = make_float4(r[0], r[1], r[2], r[3]);
            *(float4*)(dst + 4) = make_float4(r[4], r[5], r[6], r[7]);
        }
        __syncthreads();
#pragma unroll
        for (int p = 0; p < 8; ++p) {
            const int idx = p * 256 + tid;
            const int dl = idx >> 5, c4 = idx & 31;
            *(float4*)&g_xrT[((size_t)b * 256 + d0 + dl) * 512 + j0 + c4 * 4] =
                *(const float4*)&T[dl * 132 + c4 * 4];
        }
    }
}

// ---------------------------------------------------------------------------
// Kernel 2: FUSED pairwise + L/R + top-20 + softmax, in-block d-split.
// 512 threads, __launch_bounds__(512,1): 128-reg budget so the chunk's 16
// xl LDS + 4 ws loads are hoisted into registers (manual) -> full ILP.
// Accumulation op order identical to R14/R15 (loads hoisted only).
// ---------------------------------------------------------------------------
__global__ __launch_bounds__(512, 1) void pairtop_kernel(const float* __restrict__ att,
                                                         float* __restrict__ out)
{
    __shared__ double xl2d[256 * 8];   // [d][r] dup'd xl, 16KB
    __shared__ double ws2[256];        // dup'd 0.4*att, 2KB
    __shared__ float  alpha_s[8 * 512];// 16KB
    __shared__ double Rs0[256];        // half-0 partial R (packed), 2KB
    __shared__ float  Ls[8];

    const int tid = threadIdx.x;
    const int g0 = blockIdx.x * 8;
    const int b512 = g0 & ~511;
    const int b = b512 >> 9;
    const int w = tid >> 5, l = tid & 31;
    const int half = tid >> 8;            // 0 or 1
    const int jp = tid & 255;             // j-pair: j = 2jp, 2jp+1

    if (half == 0) ws2[tid] = dup2(0.4f * att[tid]);
    if (w < 8) {
        float s = 0.f;
#pragma unroll
        for (int q = 0; q < 8; ++q)
            s += att[l + 32 * q] * g_xlxr[(size_t)(g0 + w) * 512 + l + 32 * q];
#pragma unroll
        for (int off = 16; off; off >>= 1) s += __shfl_xor_sync(0xffffffffu, s, off);
        if (l == 0) Ls[w] = 0.6f * s;
    }
#pragma unroll
    for (int q = 0; q < 4; ++q) {
        const int idx = q * 512 + tid;     // 0..2047
        const int r = idx & 7, d = idx >> 3;
        xl2d[d * 8 + r] = dup2(g_xlxr[(size_t)(g0 + r) * 512 + d]);
    }
    __syncthreads();

    const int d0 = half * 128;
    const double* __restrict__ xrp =
        (const double*)g_xrT + ((size_t)b * 256 + d0) * 256 + jp;

    double acc[8];
#pragma unroll
    for (int i = 0; i < 8; ++i) acc[i] = 0.0;
    double Racc = 0.0;

    double xr[2][4];
#pragma unroll
    for (int q = 0; q < 4; ++q) xr[0][q] = xrp[(size_t)q * 256];

#pragma unroll 2
    for (int c = 0; c < 32; ++c) {
        const int cur = c & 1, nxt = cur ^ 1;
        if (c < 31) {                       // prefetch next chunk's xr (gmem)
#pragma unroll
            for (int q = 0; q < 4; ++q)
                xr[nxt][q] = xrp[(size_t)((c + 1) * 4 + q) * 256];
        }
        // hoist ALL smem loads for this chunk into registers first
        double wsd[4];
        double2 xlc[4][4];
#pragma unroll
        for (int q = 0; q < 4; ++q) {
            const int d = d0 + c * 4 + q;
            wsd[q]    = ws2[d];
            xlc[q][0] = *(const double2*)&xl2d[d * 8 + 0];
            xlc[q][1] = *(const double2*)&xl2d[d * 8 + 2];
            xlc[q][2] = *(const double2*)&xl2d[d * 8 + 4];
            xlc[q][3] = *(const double2*)&xl2d[d * 8 + 6];
        }
        // math (accumulation order identical to previous rounds)
#pragma unroll
        for (int q = 0; q < 4; ++q) {
            const double xv = xr[cur][q];
            Racc   = fma2(wsd[q], xv, Racc);
            acc[0] = fma2(wsd[q], abs2(add2(xlc[q][0].x, xv)), acc[0]);
            acc[1] = fma2(wsd[q], abs2(add2(xlc[q][0].y, xv)), acc[1]);
            acc[2] = fma2(wsd[q], abs2(add2(xlc[q][1].x, xv)), acc[2]);
            acc[3] = fma2(wsd[q], abs2(add2(xlc[q][1].y, xv)), acc[3]);
            acc[4] = fma2(wsd[q], abs2(add2(xlc[q][2].x, xv)), acc[4]);
            acc[5] = fma2(wsd[q], abs2(add2(xlc[q][2].y, xv)), acc[5]);
            acc[6] = fma2(wsd[q], abs2(add2(xlc[q][3].x, xv)), acc[6]);
            acc[7] = fma2(wsd[q], abs2(add2(xlc[q][3].y, xv)), acc[7]);
        }
    }

    if (half == 0) {
        Rs0[jp] = Racc;
#pragma unroll
        for (int r = 0; r < 8; ++r) {
            const float2 f = unpack2(acc[r]);
            *(float2*)&alpha_s[r * 512 + 2 * jp] = make_float2(f.x, f.y);
        }
    }
    __syncthreads();
    if (half == 1) {
        const float2 ra = unpack2(Rs0[jp]);
        const float2 rb = unpack2(Racc);
        const float R0 = 1.5f * (ra.x + rb.x);
        const float R1 = 1.5f * (ra.y + rb.y);
#pragma unroll
        for (int r = 0; r < 8; ++r) {
            const float2 f = unpack2(acc[r]);
            float2 p = *(const float2*)&alpha_s[r * 512 + 2 * jp];
            p.x = Ls[r] + R0 + (p.x + f.x);
            p.y = Ls[r] + R1 + (p.y + f.y);
            *(float2*)&alpha_s[r * 512 + 2 * jp] = p;
        }
    }
    __syncthreads();

    // ---- top-20 + softmax: threads 0..255, warp w handles row w ----
    if (half == 0) {
        const float* arow = &alpha_s[w * 512];
        float v[16];
#pragma unroll
        for (int t = 0; t < 16; ++t) v[t] = arow[l + 32 * t];

        float wv = 0.f; int wj = 0;
        for (int kk = 0; kk < KSEL; ++kk) {
            float bv = -INFINITY; int bt = 0;
#pragma unroll
            for (int t = 0; t < 16; ++t)
                if (v[t] > bv) { bv = v[t]; bt = t; }   // strict > keeps lowest j
            int bj = bt * 32 + l;
#pragma unroll
            for (int off = 16; off; off >>= 1) {
                const float ov = __shfl_xor_sync(0xffffffffu, bv, off);
                const int   oj = __shfl_xor_sync(0xffffffffu, bj, off);
                if (ov > bv || (ov == bv && oj < bj)) { bv = ov; bj = oj; }
            }
            if (l == kk) { wv = bv; wj = bj; }
            const int owner = bj & 31, slot = bj >> 5;
            if (l == owner) {
#pragma unroll
                for (int t = 0; t < 16; ++t)
                    if (slot == t) v[t] = -INFINITY;
            }
        }

        const float m = __shfl_sync(0xffffffffu, wv, 0);
        const float e = (l < KSEL) ? expf(wv - m) : 0.f;
        float s = e;
#pragma unroll
        for (int off = 16; off; off >>= 1) s += __shfl_xor_sync(0xffffffffu, s, off);
        if (l < KSEL) {
            const int g = g0 + w;
            const int base = g * KSEL + l;
            out[base]                   = (float)g;             // index_i
            out[NTOT * KSEL + base]     = (float)(b512 + wj);   // index_j
            out[2 * NTOT * KSEL + base] = e / s;                // attention
        }
    }
}

// ---------------------------------------------------------------------------
extern "C" void kernel_launch(void* const* d_in, const int* in_sizes, int n_in,
                              void* d_out, int out_size)
{
    const float* x   = (const float*)d_in[0];
    const float* Wl  = (const float*)d_in[3];
    const float* bl  = (const float*)d_in[4];
    const float* Wr  = (const float*)d_in[5];
    const float* br  = (const float*)d_in[6];
    const float* att = (const float*)d_in[7];
    float* out = (float*)d_out;

    proj_kernel<<<dim3(16, 8), 256>>>(x, Wl, bl, Wr, br);
    pairtop_kernel<<<256, 512>>>(att, out);
}

// round 17
// speedup vs baseline: 1.1379x; 1.1379x over previous
#include <cuda_runtime.h>
#include <math.h>

#define NTOT 2048          // B*N
#define KSEL 20

__device__ float  g_xlxr[NTOT * 512];     // [g][0:256)=xl (xr half unused)
__device__ float  g_xrT[4 * 256 * 512];   // [b][d][j] transposed xr

// ---------------- packed f32x2 helpers ----------------
__device__ __forceinline__ double fma2(double a, double b, double c) {
    double d;
    asm("fma.rn.f32x2 %0, %1, %2, %3;" : "=d"(d) : "d"(a), "d"(b), "d"(c));
    return d;
}
__device__ __forceinline__ double add2(double a, double b) {
    double d;
    asm("add.rn.f32x2 %0, %1, %2;" : "=d"(d) : "d"(a), "d"(b));
    return d;
}
__device__ __forceinline__ double abs2(double a) {
    return __longlong_as_double(__double_as_longlong(a) & 0x7fffffff7fffffffULL);
}
__device__ __forceinline__ double dup2(float v) {
    double d;
    asm("mov.b64 %0, {%1, %1};" : "=d"(d) : "f"(v));
    return d;
}
__device__ __forceinline__ float2 unpack2(double a) {
    float2 f;
    asm("mov.b64 {%0, %1}, %2;" : "=f"(f.x), "=f"(f.y) : "d"(a));
    return f;
}

// ---------------------------------------------------------------------------
// Kernel 1: FULL-K projection GEMM + fused output routing (R15, unchanged).
// ---------------------------------------------------------------------------
#define AS_OFF(s) ((s) * 2112)            // 16*132
#define BS_OFF(s) (4224 + (s) * 1088)     // 16*68

__global__ __launch_bounds__(256, 3) void proj_kernel(
    const float* __restrict__ x,
    const float* __restrict__ Wl, const float* __restrict__ bl,
    const float* __restrict__ Wr, const float* __restrict__ br)
{
    __shared__ __align__(16) float pool[8448];   // max(6400 gemm, 8448 T)
    const int tid = threadIdx.x;
    const int tx = tid & 15;
    const int ty = tid >> 4;
    const int g0 = blockIdx.x * 128;
    const int n0 = blockIdx.y * 64;
    const float* W    = (n0 < 256) ? Wl : Wr;
    const float* bias = (n0 < 256) ? bl : br;
    const int nw0 = (n0 < 256) ? n0 : n0 - 256;

    const int lmA = tid >> 1;
    const int lkA = (tid & 1) * 8;
    const int lmB = tid >> 2;
    const int lkB = (tid & 3) * 4;

    const float* xp = &x[(g0 + lmA) * 256 + lkA];
    const float* wp = &W[(nw0 + lmB) * 256 + lkB];

    double acc[8][2];
#pragma unroll
    for (int i = 0; i < 8; ++i) { acc[i][0] = 0.0; acc[i][1] = 0.0; }

    float4 a0 = *(const float4*)xp;
    float4 a1 = *(const float4*)(xp + 4);
    float4 bv = *(const float4*)wp;
    {
        float* A = pool + AS_OFF(0); float* B = pool + BS_OFF(0);
        A[(lkA + 0) * 132 + lmA] = a0.x; A[(lkA + 1) * 132 + lmA] = a0.y;
        A[(lkA + 2) * 132 + lmA] = a0.z; A[(lkA + 3) * 132 + lmA] = a0.w;
        A[(lkA + 4) * 132 + lmA] = a1.x; A[(lkA + 5) * 132 + lmA] = a1.y;
        A[(lkA + 6) * 132 + lmA] = a1.z; A[(lkA + 7) * 132 + lmA] = a1.w;
        B[(lkB + 0) * 68 + lmB] = bv.x;  B[(lkB + 1) * 68 + lmB] = bv.y;
        B[(lkB + 2) * 68 + lmB] = bv.z;  B[(lkB + 3) * 68 + lmB] = bv.w;
    }
    a0 = *(const float4*)(xp + 16);
    a1 = *(const float4*)(xp + 20);
    bv = *(const float4*)(wp + 16);

#pragma unroll 1
    for (int t = 0; t < 16; ++t) {
        __syncthreads();
        if (t < 15) {
            float* A = pool + AS_OFF((t + 1) & 1); float* B = pool + BS_OFF((t + 1) & 1);
            A[(lkA + 0) * 132 + lmA] = a0.x; A[(lkA + 1) * 132 + lmA] = a0.y;
            A[(lkA + 2) * 132 + lmA] = a0.z; A[(lkA + 3) * 132 + lmA] = a0.w;
            A[(lkA + 4) * 132 + lmA] = a1.x; A[(lkA + 5) * 132 + lmA] = a1.y;
            A[(lkA + 6) * 132 + lmA] = a1.z; A[(lkA + 7) * 132 + lmA] = a1.w;
            B[(lkB + 0) * 68 + lmB] = bv.x;  B[(lkB + 1) * 68 + lmB] = bv.y;
            B[(lkB + 2) * 68 + lmB] = bv.z;  B[(lkB + 3) * 68 + lmB] = bv.w;
        }
        if (t < 14) {
            a0 = *(const float4*)(xp + (t + 2) * 16);
            a1 = *(const float4*)(xp + (t + 2) * 16 + 4);
            bv = *(const float4*)(wp + (t + 2) * 16);
        }
        const float* A = pool + AS_OFF(t & 1); const float* B = pool + BS_OFF(t & 1);
#pragma unroll
        for (int k = 0; k < 16; ++k) {
            const float4 r0 = *(const float4*)&A[k * 132 + ty * 8];
            const float4 r1 = *(const float4*)&A[k * 132 + ty * 8 + 4];
            const double2 b2 = *(const double2*)&B[k * 68 + tx * 4];
            double d;
            d = dup2(r0.x); acc[0][0] = fma2(d, b2.x, acc[0][0]);
                            acc[0][1] = fma2(d, b2.y, acc[0][1]);
            d = dup2(r0.y); acc[1][0] = fma2(d, b2.x, acc[1][0]);
                            acc[1][1] = fma2(d, b2.y, acc[1][1]);
            d = dup2(r0.z); acc[2][0] = fma2(d, b2.x, acc[2][0]);
                            acc[2][1] = fma2(d, b2.y, acc[2][1]);
            d = dup2(r0.w); acc[3][0] = fma2(d, b2.x, acc[3][0]);
                            acc[3][1] = fma2(d, b2.y, acc[3][1]);
            d = dup2(r1.x); acc[4][0] = fma2(d, b2.x, acc[4][0]);
                            acc[4][1] = fma2(d, b2.y, acc[4][1]);
            d = dup2(r1.y); acc[5][0] = fma2(d, b2.x, acc[5][0]);
                            acc[5][1] = fma2(d, b2.y, acc[5][1]);
            d = dup2(r1.z); acc[6][0] = fma2(d, b2.x, acc[6][0]);
                            acc[6][1] = fma2(d, b2.y, acc[6][1]);
            d = dup2(r1.w); acc[7][0] = fma2(d, b2.x, acc[7][0]);
                            acc[7][1] = fma2(d, b2.y, acc[7][1]);
        }
    }

    const float b0 = bias[nw0 + tx * 4 + 0];
    const float b1 = bias[nw0 + tx * 4 + 1];
    const float b2f = bias[nw0 + tx * 4 + 2];
    const float b3 = bias[nw0 + tx * 4 + 3];

    if (n0 < 256) {
#pragma unroll
        for (int i = 0; i < 8; ++i) {
            const int row = g0 + ty * 8 + i;
            const float2 p0 = unpack2(acc[i][0]);
            const float2 p1 = unpack2(acc[i][1]);
            *(float4*)&g_xlxr[(size_t)row * 512 + n0 + tx * 4] =
                make_float4(p0.x + b0, p0.y + b1, p1.x + b2f, p1.y + b3);
        }
    } else {
        const int d0 = n0 - 256;
        const int b = g0 >> 9;
        const int j0 = g0 & 511;
        __syncthreads();
        float* T = pool;                  // [64 d][132 j-stride]
#pragma unroll
        for (int c = 0; c < 4; ++c) {
            float r[8];
#pragma unroll
            for (int i = 0; i < 8; ++i) {
                const float2 p = unpack2(acc[i][c >> 1]);
                r[i] = ((c & 1) ? p.y : p.x) + ((c == 0) ? b0 : (c == 1) ? b1
                                              : (c == 2) ? b2f : b3);
            }
            float* dst = &T[(tx * 4 + c) * 132 + ty * 8];
            *(float4*)dst       = make_float4(r[0], r[1], r[2], r[3]);
            *(float4*)(dst + 4) = make_float4(r[4], r[5], r[6], r[7]);
        }
        __syncthreads();
#pragma unroll
        for (int p = 0; p < 8; ++p) {
            const int idx = p * 256 + tid;
            const int dl = idx >> 5, c4 = idx & 31;
            *(float4*)&g_xrT[((size_t)b * 256 + d0 + dl) * 512 + j0 + c4 * 4] =
                *(const float4*)&T[dl * 132 + c4 * 4];
        }
    }
}

// ---------------------------------------------------------------------------
// Kernel 2: FUSED pairwise + L/R + top-20 + softmax, in-block d-split.
// GRID 296 = 148*2 (perfect 2 blocks/SM): per batch 68 blocks x 7 rows +
// 6 blocks x 6 rows. 512 threads; half h accumulates d in [h*128,h*128+128).
// Thread owns ONE j-pair x up-to-7 rows. R15 register shape (no hoist).
// ---------------------------------------------------------------------------
__global__ void pairtop_kernel(const float* __restrict__ att,
                               float* __restrict__ out)
{
    __shared__ double xl2d[256 * 8];   // [d][slot 0..7] dup'd xl, 16KB
    __shared__ double ws2[256];        // dup'd 0.4*att, 2KB
    __shared__ float  alpha_s[8 * 512];// 16KB
    __shared__ double Rs0[256];        // half-0 partial R (packed), 2KB
    __shared__ float  Ls[8];

    const int tid = threadIdx.x;
    const int bid = blockIdx.x;           // 0..295
    const int b   = bid / 74;
    const int u   = bid % 74;
    const int nr  = (u < 68) ? 7 : 6;
    const int r0  = (u < 68) ? u * 7 : 476 + (u - 68) * 6;
    const int g0  = b * 512 + r0;
    const int b512 = b * 512;
    const int w = tid >> 5, l = tid & 31;
    const int half = tid >> 8;            // 0 or 1
    const int jp = tid & 255;             // j-pair: j = 2jp, 2jp+1

    if (half == 0) ws2[tid] = dup2(0.4f * att[tid]);
    // L_i: warp w (<8) computes 0.6 * dot(att, xl[row]) (clamped; used w<nr)
    if (w < 8) {
        const int rw = (w < nr) ? w : nr - 1;
        float s = 0.f;
#pragma unroll
        for (int q = 0; q < 8; ++q)
            s += att[l + 32 * q] * g_xlxr[(size_t)(g0 + rw) * 512 + l + 32 * q];
#pragma unroll
        for (int off = 16; off; off >>= 1) s += __shfl_xor_sync(0xffffffffu, s, off);
        if (l == 0) Ls[w] = 0.6f * s;
    }
#pragma unroll
    for (int q = 0; q < 4; ++q) {
        const int idx = q * 512 + tid;     // 0..2047
        const int r = idx & 7, d = idx >> 3;
        const int rr = (r < nr) ? r : nr - 1;   // clamp slots >= nr
        xl2d[d * 8 + r] = dup2(g_xlxr[(size_t)(g0 + rr) * 512 + d]);
    }
    __syncthreads();

    const int d0 = half * 128;
    const double* __restrict__ xrp =
        (const double*)g_xrT + ((size_t)b * 256 + d0) * 256 + jp;

    double acc[7];
#pragma unroll
    for (int i = 0; i < 7; ++i) acc[i] = 0.0;
    double Racc = 0.0;

    double xr[2][4];
#pragma unroll
    for (int q = 0; q < 4; ++q) xr[0][q] = xrp[(size_t)q * 256];

#pragma unroll 2
    for (int c = 0; c < 32; ++c) {
        const int cur = c & 1, nxt = cur ^ 1;
        if (c < 31) {                       // prefetch next chunk's xr
#pragma unroll
            for (int q = 0; q < 4; ++q)
                xr[nxt][q] = xrp[(size_t)((c + 1) * 4 + q) * 256];
        }
#pragma unroll
        for (int q = 0; q < 4; ++q) {
            const int d = d0 + c * 4 + q;
            const double wsd = ws2[d];
            const double2 x01 = *(const double2*)&xl2d[d * 8 + 0];
            const double2 x23 = *(const double2*)&xl2d[d * 8 + 2];
            const double2 x45 = *(const double2*)&xl2d[d * 8 + 4];
            const double2 x67 = *(const double2*)&xl2d[d * 8 + 6];
            const double xv = xr[cur][q];
            Racc   = fma2(wsd, xv, Racc);
            acc[0] = fma2(wsd, abs2(add2(x01.x, xv)), acc[0]);
            acc[1] = fma2(wsd, abs2(add2(x01.y, xv)), acc[1]);
            acc[2] = fma2(wsd, abs2(add2(x23.x, xv)), acc[2]);
            acc[3] = fma2(wsd, abs2(add2(x23.y, xv)), acc[3]);
            acc[4] = fma2(wsd, abs2(add2(x45.x, xv)), acc[4]);
            acc[5] = fma2(wsd, abs2(add2(x45.y, xv)), acc[5]);
            acc[6] = fma2(wsd, abs2(add2(x67.x, xv)), acc[6]);
        }
    }

    if (half == 0) {
        Rs0[jp] = Racc;
#pragma unroll
        for (int r = 0; r < 7; ++r) {
            const float2 f = unpack2(acc[r]);
            *(float2*)&alpha_s[r * 512 + 2 * jp] = make_float2(f.x, f.y);
        }
    }
    __syncthreads();
    if (half == 1) {
        const float2 ra = unpack2(Rs0[jp]);
        const float2 rb = unpack2(Racc);
        const float R0 = 1.5f * (ra.x + rb.x);
        const float R1 = 1.5f * (ra.y + rb.y);
#pragma unroll
        for (int r = 0; r < 7; ++r) {
            const float2 f = unpack2(acc[r]);
            float2 p = *(const float2*)&alpha_s[r * 512 + 2 * jp];
            p.x = Ls[r] + R0 + (p.x + f.x);
            p.y = Ls[r] + R1 + (p.y + f.y);
            *(float2*)&alpha_s[r * 512 + 2 * jp] = p;
        }
    }
    __syncthreads();

    // ---- top-20 + softmax: threads 0..255, warp w handles row w (w < nr) ----
    if (half == 0 && w < nr) {
        const float* arow = &alpha_s[w * 512];
        float v[16];
#pragma unroll
        for (int t = 0; t < 16; ++t) v[t] = arow[l + 32 * t];

        float wv = 0.f; int wj = 0;
        for (int kk = 0; kk < KSEL; ++kk) {
            float bv = -INFINITY; int bt = 0;
#pragma unroll
            for (int t = 0; t < 16; ++t)
                if (v[t] > bv) { bv = v[t]; bt = t; }   // strict > keeps lowest j
            int bj = bt * 32 + l;
#pragma unroll
            for (int off = 16; off; off >>= 1) {
                const float ov = __shfl_xor_sync(0xffffffffu, bv, off);
                const int   oj = __shfl_xor_sync(0xffffffffu, bj, off);
                if (ov > bv || (ov == bv && oj < bj)) { bv = ov; bj = oj; }
            }
            if (l == kk) { wv = bv; wj = bj; }
            const int owner = bj & 31, slot = bj >> 5;
            if (l == owner) {
#pragma unroll
                for (int t = 0; t < 16; ++t)
                    if (slot == t) v[t] = -INFINITY;
            }
        }

        const float m = __shfl_sync(0xffffffffu, wv, 0);
        const float e = (l < KSEL) ? expf(wv - m) : 0.f;
        float s = e;
#pragma unroll
        for (int off = 16; off; off >>= 1) s += __shfl_xor_sync(0xffffffffu, s, off);
        if (l < KSEL) {
            const int g = g0 + w;
            const int base = g * KSEL + l;
            out[base]                   = (float)g;             // index_i
            out[NTOT * KSEL + base]     = (float)(b512 + wj);   // index_j
            out[2 * NTOT * KSEL + base] = e / s;                // attention
        }
    }
}

// ---------------------------------------------------------------------------
extern "C" void kernel_launch(void* const* d_in, const int* in_sizes, int n_in,
                              void* d_out, int out_size)
{
    const float* x   = (const float*)d_in[0];
    const float* Wl  = (const float*)d_in[3];
    const float* bl  = (const float*)d_in[4];
    const float* Wr  = (const float*)d_in[5];
    const float* br  = (const float*)d_in[6];
    const float* att = (const float*)d_in[7];
    float* out = (float*)d_out;

    proj_kernel<<<dim3(16, 8), 256>>>(x, Wl, bl, Wr, br);
    pairtop_kernel<<<296, 512>>>(att, out);
}